// round 1
// baseline (speedup 1.0000x reference)
#include <cuda_runtime.h>
#include <cstdint>

#define EPSF 1e-5f

// ---------------- problem dims ----------------
#define BB 8
#define TT 128
#define UU 64
#define EE 768
#define HH 512
#define HH2 256
#define VV 1024
#define BT (BB*TT)   // 1024 rows of enc_p
#define BU (BB*UU)   // 512 rows of dec_p

// ---------------- scratch (device globals; no allocation allowed) ----------------
__device__ float g_tmp [BT*HH];
__device__ float g_encp[BT*HH];
__device__ float g_decp[BU*HH];
__device__ float g_Afe [BT*HH];   // enc_p @ Wf1^T
__device__ float g_Bfd [BU*HH];   // dec_p @ Wf1^T + bf1
__device__ float g_att [BU*HH];
__device__ float g_Catt[BU*HH];   // att @ W1[:,256:768]^T + b1
__device__ float g_WeT [EE*HH];
__device__ float g_WdT [EE*HH];
__device__ float g_Wf1T[HH*HH];
__device__ float g_WvT [HH*HH];
__device__ float g_WoT [HH*HH];
__device__ float g_W1aT[HH*HH];   // transpose of W1[:,256:768]
__device__ float g_W1fT[HH2*HH];  // transpose of W1[:,0:256]
__device__ float g_Wf2T[HH*HH2];
__device__ float g_W2Ts[HH*VV];   // transpose of W2, columns pre-scaled by ssw
__device__ float g_b2s [VV];      // b2 * ssw

// ---------------- small helpers ----------------
__device__ __forceinline__ float warp_sum(float v) {
#pragma unroll
    for (int o = 16; o; o >>= 1) v += __shfl_xor_sync(0xffffffffu, v, o);
    return v;
}

__device__ __forceinline__ unsigned long long pack2(float a, float b) {
    unsigned long long r;
    asm("mov.b64 %0, {%1, %2};" : "=l"(r) : "f"(a), "f"(b));
    return r;
}
__device__ __forceinline__ float2 unpack2(unsigned long long v) {
    float2 f;
    asm("mov.b64 {%0, %1}, %2;" : "=f"(f.x), "=f"(f.y) : "l"(v));
    return f;
}
// packed fp32x2 FMA: d += a*b (elementwise on 2 lanes) — full-rate fp32 on Blackwell
__device__ __forceinline__ void ffma2(unsigned long long& d, unsigned long long a, unsigned long long b) {
    asm("fma.rn.f32x2 %0, %1, %2, %0;" : "+l"(d) : "l"(a), "l"(b));
}

__device__ __forceinline__ void cp16(float* s, const float* g) {
    unsigned ss = (unsigned)__cvta_generic_to_shared(s);
    asm volatile("cp.async.cg.shared.global [%0], [%1], 16;\n" :: "r"(ss), "l"(g));
}
__device__ __forceinline__ void cp_commit() { asm volatile("cp.async.commit_group;\n"); }
template <int N>
__device__ __forceinline__ void cp_wait() { asm volatile("cp.async.wait_group %0;\n" :: "n"(N)); }

// ---------------- weight transpose:  WT[k*Nout + o] = W[o*ldw + koff + k] * scale[o]? ----------------
__global__ void transpose_k(const float* __restrict__ W, float* __restrict__ WT,
                            int Nout, int Kdim, int ldw, int koff,
                            const float* __restrict__ scale) {
    __shared__ float t[32][33];
    int k0 = blockIdx.x * 32, o0 = blockIdx.y * 32;
    int x = threadIdx.x, y = threadIdx.y;  // block (32,8)
#pragma unroll
    for (int yy = y; yy < 32; yy += 8) {
        int o = o0 + yy, k = k0 + x;
        float v = W[o * ldw + koff + k];
        if (scale) v *= scale[o];
        t[yy][x] = v;
    }
    __syncthreads();
#pragma unroll
    for (int yy = y; yy < 32; yy += 8) {
        int k = k0 + yy, o = o0 + x;
        WT[k * Nout + o] = t[x][yy];
    }
}

__global__ void scale_bias_k(const float* __restrict__ b2, const float* __restrict__ ssw,
                             float* __restrict__ out) {
    int i = threadIdx.x + blockIdx.x * blockDim.x;
    if (i < VV) out[i] = b2[i] * ssw[i];
}

// ---------------- small GEMM: out[M,N] = X[M,K] @ WT + bias ----------------
// grid (M/64, N/256), block 256. WT is [K][N] row-major (ldw = total N of WT).
__global__ void __launch_bounds__(256) gemm_nt(
    const float* __restrict__ X, int ldx,
    const float* __restrict__ WT, int ldw,
    const float* __restrict__ bias,
    float* __restrict__ out, int ldo, int K) {
    __shared__ float Xs[64 * 16];
    __shared__ float Ws[16 * 256];
    int tid = threadIdx.x, tx = tid & 31, ty = tid >> 5;
    int row0 = blockIdx.x * 64, col0 = blockIdx.y * 256;
    float acc[8][8];
    if (bias) {
#pragma unroll
        for (int j = 0; j < 8; j++) {
            float bv = bias[col0 + tx * 8 + j];
#pragma unroll
            for (int i = 0; i < 8; i++) acc[i][j] = bv;
        }
    } else {
#pragma unroll
        for (int i = 0; i < 8; i++)
#pragma unroll
            for (int j = 0; j < 8; j++) acc[i][j] = 0.f;
    }
    for (int kt = 0; kt < K; kt += 16) {
        {   // stage X tile 64x16
            int f = tid, r = f >> 2, k4 = (f & 3) << 2;
            *(float4*)&Xs[r * 16 + k4] = *(const float4*)&X[(row0 + r) * ldx + kt + k4];
        }
#pragma unroll
        for (int i = 0; i < 4; i++) {  // stage W tile 16x256
            int f = tid + 256 * i, r = f >> 6, c4 = (f & 63) << 2;
            *(float4*)&Ws[r * 256 + c4] = *(const float4*)&WT[(kt + r) * ldw + col0 + c4];
        }
        __syncthreads();
#pragma unroll
        for (int kk4 = 0; kk4 < 16; kk4 += 4) {
            float4 a4[8];
#pragma unroll
            for (int i = 0; i < 8; i++) a4[i] = *(const float4*)&Xs[(ty * 8 + i) * 16 + kk4];
#pragma unroll
            for (int kc = 0; kc < 4; kc++) {
                const float* wr = &Ws[(kk4 + kc) * 256 + tx * 8];
                float4 w0 = *(const float4*)wr, w1 = *(const float4*)(wr + 4);
#pragma unroll
                for (int i = 0; i < 8; i++) {
                    float a = (kc == 0) ? a4[i].x : (kc == 1) ? a4[i].y : (kc == 2) ? a4[i].z : a4[i].w;
                    acc[i][0] += a * w0.x; acc[i][1] += a * w0.y;
                    acc[i][2] += a * w0.z; acc[i][3] += a * w0.w;
                    acc[i][4] += a * w1.x; acc[i][5] += a * w1.y;
                    acc[i][6] += a * w1.z; acc[i][7] += a * w1.w;
                }
            }
        }
        __syncthreads();
    }
#pragma unroll
    for (int i = 0; i < 8; i++) {
        float* orow = out + (size_t)(row0 + ty * 8 + i) * ldo + col0 + tx * 8;
        *(float4*)orow       = make_float4(acc[i][0], acc[i][1], acc[i][2], acc[i][3]);
        *(float4*)(orow + 4) = make_float4(acc[i][4], acc[i][5], acc[i][6], acc[i][7]);
    }
}

// ---------------- standalone LayerNorm+ReLU over rows ----------------
__global__ void ln_relu_k(const float* __restrict__ in, float* __restrict__ out,
                          const float* __restrict__ g, const float* __restrict__ b, int N) {
    int row = blockIdx.x * 8 + (threadIdx.x >> 5);
    int tx = threadIdx.x & 31;
    const float* x = in + (size_t)row * N;
    float s = 0.f, sq = 0.f;
    for (int j = tx; j < N; j += 32) { float v = x[j]; s += v; sq += v * v; }
    s = warp_sum(s); sq = warp_sum(sq);
    float m = s / N, var = sq / N - m * m, rs = rsqrtf(var + EPSF);
    float* y = out + (size_t)row * N;
    for (int j = tx; j < N; j += 32) {
        float v = (x[j] - m) * rs * g[j] + b[j];
        y[j] = fmaxf(v, 0.f);
    }
}

// ---------------- fused main kernel machinery ----------------
// GEMM chunk: acc[8][4](f32x2 pairs) += acts[64 x KDIM](smem) @ wT[KDIM x 256](gmem, ldw)
// 8x8 micro-tile per thread: rows ty*8.., cols tx*8.. . Weight tiles 16x256 double-buffered via cp.async.
template <int KDIM, int AST>
__device__ __forceinline__ void gemm_chunk(
    const float* __restrict__ wT, int ldw,
    const float* __restrict__ acts, float* __restrict__ wst,
    unsigned long long acc[8][4], int tid, int tx, int ty) {
    constexpr int NT = KDIM / 16;
    auto stage = [&](int kt, int sel) {
#pragma unroll
        for (int i = 0; i < 4; i++) {
            int f = tid + 256 * i, r = f >> 6, c4 = (f & 63) << 2;
            cp16(wst + sel * 4096 + r * 256 + c4, wT + (size_t)(kt * 16 + r) * ldw + c4);
        }
        cp_commit();
    };
    stage(0, 0);
#pragma unroll 1
    for (int kt = 0; kt < NT; ++kt) {
        int sel = kt & 1;
        if (kt + 1 < NT) { stage(kt + 1, sel ^ 1); cp_wait<1>(); }
        else             { cp_wait<0>(); }
        __syncthreads();
        const float* wb = wst + sel * 4096;
#pragma unroll
        for (int kk4 = 0; kk4 < 16; kk4 += 4) {
            float4 a4[8];
#pragma unroll
            for (int i = 0; i < 8; i++)
                a4[i] = *(const float4*)(acts + (ty * 8 + i) * AST + kt * 16 + kk4);
#pragma unroll
            for (int kc = 0; kc < 4; kc++) {
                const float* wr = wb + (kk4 + kc) * 256 + tx * 8;
                ulonglong2 wlo = *(const ulonglong2*)wr;
                ulonglong2 whi = *(const ulonglong2*)(wr + 4);
#pragma unroll
                for (int i = 0; i < 8; i++) {
                    float av = (kc == 0) ? a4[i].x : (kc == 1) ? a4[i].y : (kc == 2) ? a4[i].z : a4[i].w;
                    unsigned long long ap = pack2(av, av);
                    ffma2(acc[i][0], ap, wlo.x);
                    ffma2(acc[i][1], ap, wlo.y);
                    ffma2(acc[i][2], ap, whi.x);
                    ffma2(acc[i][3], ap, whi.y);
                }
            }
        }
        __syncthreads();
    }
}

__device__ __forceinline__ void ln_relu_smem(float* buf, int ncol,
                                             const float* __restrict__ g,
                                             const float* __restrict__ b, int tx, int ty) {
#pragma unroll 1
    for (int r = 0; r < 8; r++) {
        int row = ty * 8 + r;
        float* x = buf + row * ncol;
        float s = 0.f, sq = 0.f;
        for (int j = tx; j < ncol; j += 32) { float v = x[j]; s += v; sq += v * v; }
        s = warp_sum(s); sq = warp_sum(sq);
        float m = s / ncol, var = sq / ncol - m * m, rs = rsqrtf(var + EPSF);
        for (int j = tx; j < ncol; j += 32) {
            float v = (x[j] - m) * rs * g[j] + b[j];
            x[j] = fmaxf(v, 0.f);
        }
    }
}

// One CTA per (b,t): rows = all 64 u. SMEM: bufA 64x512, bufB 64x256, wst 2x16x256.
__global__ void __launch_bounds__(256, 1) fused_main(
    const float* __restrict__ Afe, const float* __restrict__ Bfd, const float* __restrict__ Catt,
    const float* __restrict__ gf1, const float* __restrict__ bnf1,
    const float* __restrict__ Wf2T, const float* __restrict__ bf2,
    const float* __restrict__ gf2, const float* __restrict__ bnf2,
    const float* __restrict__ W1fT, const float* __restrict__ g1v, const float* __restrict__ bn1,
    const float* __restrict__ W2Ts, const float* __restrict__ b2s,
    float* __restrict__ out) {
    extern __shared__ float smem[];
    float* bufA = smem;                   // 64*512
    float* bufB = smem + 64 * 512;        // 64*256
    float* wst  = bufB + 64 * 256;        // 2*16*256

    int tid = threadIdx.x, tx = tid & 31, ty = tid >> 5;
    int bt = blockIdx.x;        // b*T + t
    int b  = bt >> 7;

    // ---- Stage A: f = relu(LN(Afe[b,t] + Bfd[b,u])), into bufA ----
    {
        const float* Ar = Afe + (size_t)bt * HH;
#pragma unroll 1
        for (int r = 0; r < 8; r++) {
            int u = ty * 8 + r;
            const float* Br = Bfd + (size_t)(b * UU + u) * HH;
            float v[16]; float s = 0.f, sq = 0.f;
#pragma unroll
            for (int jj = 0; jj < 16; jj++) {
                int j = tx + jj * 32;
                float x = Ar[j] + Br[j];
                v[jj] = x; s += x; sq += x * x;
            }
            s = warp_sum(s); sq = warp_sum(sq);
            float m = s * (1.f / HH), var = sq * (1.f / HH) - m * m, rs = rsqrtf(var + EPSF);
#pragma unroll
            for (int jj = 0; jj < 16; jj++) {
                int j = tx + jj * 32;
                float y = (v[jj] - m) * rs * gf1[j] + bnf1[j];
                bufA[u * HH + j] = fmaxf(y, 0.f);
            }
        }
    }
    __syncthreads();

    // ---- Stage B: fused = relu(LN(f @ Wf2T + bf2)) [64 x 256] into bufB ----
    {
        unsigned long long acc[8][4];
        int c0 = tx * 8;
        ulonglong2 blo = *(const ulonglong2*)&bf2[c0];
        ulonglong2 bhi = *(const ulonglong2*)&bf2[c0 + 4];
#pragma unroll
        for (int i = 0; i < 8; i++) { acc[i][0] = blo.x; acc[i][1] = blo.y; acc[i][2] = bhi.x; acc[i][3] = bhi.y; }
        gemm_chunk<HH, HH>(Wf2T, HH2, bufA, wst, acc, tid, tx, ty);
#pragma unroll
        for (int i = 0; i < 8; i++) {
            int u = ty * 8 + i;
            float2 p0 = unpack2(acc[i][0]), p1 = unpack2(acc[i][1]);
            float2 p2 = unpack2(acc[i][2]), p3 = unpack2(acc[i][3]);
            *(float4*)&bufB[u * HH2 + c0]     = make_float4(p0.x, p0.y, p1.x, p1.y);
            *(float4*)&bufB[u * HH2 + c0 + 4] = make_float4(p2.x, p2.y, p3.x, p3.y);
        }
    }
    __syncthreads();
    ln_relu_smem(bufB, HH2, gf2, bnf2, tx, ty);
    __syncthreads();

    // ---- Stage C: h_pre = fused @ W1fT + Catt[b,u]; h = relu(LN(h_pre)) into bufA ----
#pragma unroll 1
    for (int cc = 0; cc < 2; ++cc) {
        int colbase = cc * 256;
        int c0 = colbase + tx * 8;
        unsigned long long acc[8][4];
#pragma unroll
        for (int i = 0; i < 8; i++) {
            int u = ty * 8 + i;
            const ulonglong2* cp = (const ulonglong2*)&Catt[(size_t)(b * UU + u) * HH + c0];
            acc[i][0] = cp[0].x; acc[i][1] = cp[0].y; acc[i][2] = cp[1].x; acc[i][3] = cp[1].y;
        }
        gemm_chunk<HH2, HH2>(W1fT + colbase, HH, bufB, wst, acc, tid, tx, ty);
#pragma unroll
        for (int i = 0; i < 8; i++) {
            int u = ty * 8 + i;
            float2 p0 = unpack2(acc[i][0]), p1 = unpack2(acc[i][1]);
            float2 p2 = unpack2(acc[i][2]), p3 = unpack2(acc[i][3]);
            *(float4*)&bufA[u * HH + c0]     = make_float4(p0.x, p0.y, p1.x, p1.y);
            *(float4*)&bufA[u * HH + c0 + 4] = make_float4(p2.x, p2.y, p3.x, p3.y);
        }
    }
    __syncthreads();
    ln_relu_smem(bufA, HH, g1v, bn1, tx, ty);
    __syncthreads();

    // ---- Stage D: logits = h @ W2Ts + b2s, straight to gmem ----
#pragma unroll 1
    for (int cc = 0; cc < 4; ++cc) {
        int colbase = cc * 256;
        int c0 = colbase + tx * 8;
        unsigned long long acc[8][4];
        ulonglong2 blo = *(const ulonglong2*)&b2s[c0];
        ulonglong2 bhi = *(const ulonglong2*)&b2s[c0 + 4];
#pragma unroll
        for (int i = 0; i < 8; i++) { acc[i][0] = blo.x; acc[i][1] = blo.y; acc[i][2] = bhi.x; acc[i][3] = bhi.y; }
        gemm_chunk<HH, HH>(W2Ts + colbase, VV, bufA, wst, acc, tid, tx, ty);
#pragma unroll
        for (int i = 0; i < 8; i++) {
            int u = ty * 8 + i;
            float* orow = out + (size_t)(bt * UU + u) * VV + c0;
            float2 p0 = unpack2(acc[i][0]), p1 = unpack2(acc[i][1]);
            float2 p2 = unpack2(acc[i][2]), p3 = unpack2(acc[i][3]);
            *(float4*)orow       = make_float4(p0.x, p0.y, p1.x, p1.y);
            *(float4*)(orow + 4) = make_float4(p2.x, p2.y, p3.x, p3.y);
        }
    }
}

// ---------------- host launcher ----------------
extern "C" void kernel_launch(void* const* d_in, const int* in_sizes, int n_in,
                              void* d_out, int out_size) {
    const float* enc = (const float*)d_in[0];
    const float* dec = (const float*)d_in[1];
    const float* We  = (const float*)d_in[2];
    const float* be  = (const float*)d_in[3];
    const float* ge  = (const float*)d_in[4];
    const float* bne = (const float*)d_in[5];
    const float* Wd  = (const float*)d_in[6];
    const float* bd  = (const float*)d_in[7];
    const float* gd  = (const float*)d_in[8];
    const float* bnd = (const float*)d_in[9];
    const float* Wf1 = (const float*)d_in[10];
    const float* bf1 = (const float*)d_in[11];
    const float* gf1 = (const float*)d_in[12];
    const float* bnf1= (const float*)d_in[13];
    const float* Wf2 = (const float*)d_in[14];
    const float* bf2 = (const float*)d_in[15];
    const float* gf2 = (const float*)d_in[16];
    const float* bnf2= (const float*)d_in[17];
    const float* Wv  = (const float*)d_in[18];
    const float* bv  = (const float*)d_in[19];
    const float* Wo  = (const float*)d_in[20];
    const float* bo  = (const float*)d_in[21];
    const float* W1  = (const float*)d_in[22];
    const float* b1  = (const float*)d_in[23];
    const float* g1  = (const float*)d_in[24];
    const float* bn1 = (const float*)d_in[25];
    const float* W2  = (const float*)d_in[26];
    const float* b2  = (const float*)d_in[27];
    const float* ssw = (const float*)d_in[28];
    float* out = (float*)d_out;

    float *tmp, *encp, *decp, *Afe, *Bfd, *att, *Catt;
    float *WeT, *WdT, *Wf1T, *WvT, *WoT, *W1aT, *W1fT, *Wf2T, *W2Ts, *b2s;
    cudaGetSymbolAddress((void**)&tmp,  g_tmp);
    cudaGetSymbolAddress((void**)&encp, g_encp);
    cudaGetSymbolAddress((void**)&decp, g_decp);
    cudaGetSymbolAddress((void**)&Afe,  g_Afe);
    cudaGetSymbolAddress((void**)&Bfd,  g_Bfd);
    cudaGetSymbolAddress((void**)&att,  g_att);
    cudaGetSymbolAddress((void**)&Catt, g_Catt);
    cudaGetSymbolAddress((void**)&WeT,  g_WeT);
    cudaGetSymbolAddress((void**)&WdT,  g_WdT);
    cudaGetSymbolAddress((void**)&Wf1T, g_Wf1T);
    cudaGetSymbolAddress((void**)&WvT,  g_WvT);
    cudaGetSymbolAddress((void**)&WoT,  g_WoT);
    cudaGetSymbolAddress((void**)&W1aT, g_W1aT);
    cudaGetSymbolAddress((void**)&W1fT, g_W1fT);
    cudaGetSymbolAddress((void**)&Wf2T, g_Wf2T);
    cudaGetSymbolAddress((void**)&W2Ts, g_W2Ts);
    cudaGetSymbolAddress((void**)&b2s,  g_b2s);

    dim3 tb(32, 8);
    // weight transposes
    transpose_k<<<dim3(EE/32, HH/32), tb>>>(We,  WeT,  HH,  EE,  EE, 0,   nullptr);
    transpose_k<<<dim3(EE/32, HH/32), tb>>>(Wd,  WdT,  HH,  EE,  EE, 0,   nullptr);
    transpose_k<<<dim3(HH/32, HH/32), tb>>>(Wf1, Wf1T, HH,  HH,  HH, 0,   nullptr);
    transpose_k<<<dim3(HH/32, HH/32), tb>>>(Wv,  WvT,  HH,  HH,  HH, 0,   nullptr);
    transpose_k<<<dim3(HH/32, HH/32), tb>>>(Wo,  WoT,  HH,  HH,  HH, 0,   nullptr);
    transpose_k<<<dim3(HH/32, HH/32), tb>>>(W1,  W1aT, HH,  HH,  EE, HH2, nullptr);
    transpose_k<<<dim3(HH2/32,HH/32), tb>>>(W1,  W1fT, HH,  HH2, EE, 0,   nullptr);
    transpose_k<<<dim3(HH/32, HH2/32),tb>>>(Wf2, Wf2T, HH2, HH,  HH, 0,   nullptr);
    transpose_k<<<dim3(HH/32, VV/32), tb>>>(W2,  W2Ts, VV,  HH,  HH, 0,   ssw);
    scale_bias_k<<<1, VV>>>(b2, ssw, b2s);

    // projections: enc_p, dec_p
    gemm_nt<<<dim3(BT/64, HH/256), 256>>>(enc, EE, WeT, HH, be, tmp, HH, EE);
    ln_relu_k<<<BT/8, 256>>>(tmp, encp, ge, bne, HH);
    gemm_nt<<<dim3(BU/64, HH/256), 256>>>(dec, EE, WdT, HH, bd, tmp, HH, EE);
    ln_relu_k<<<BU/8, 256>>>(tmp, decp, gd, bnd, HH);

    // Wf1 factorization: Afe = enc_p@Wf1^T ; Bfd = dec_p@Wf1^T + bf1
    gemm_nt<<<dim3(BT/64, HH/256), 256>>>(encp, HH, Wf1T, HH, nullptr, Afe, HH, HH);
    gemm_nt<<<dim3(BU/64, HH/256), 256>>>(decp, HH, Wf1T, HH, bf1, Bfd, HH, HH);

    // attention branch (softmax over 1 key == identity): att = (dec_p@Wv^T+bv)@Wo^T+bo
    gemm_nt<<<dim3(BU/64, HH/256), 256>>>(decp, HH, WvT, HH, bv, tmp, HH, HH);
    gemm_nt<<<dim3(BU/64, HH/256), 256>>>(tmp, HH, WoT, HH, bo, att, HH, HH);
    // Catt = att @ W1[:,256:768]^T + b1  (per-(b,u) bias for stage h)
    gemm_nt<<<dim3(BU/64, HH/256), 256>>>(att, HH, W1aT, HH, b1, Catt, HH, HH);

    // fused main pipeline: one CTA per (b,t), 64 u-rows
    int smem = (64 * HH + 64 * HH2 + 2 * 16 * 256) * 4;  // 229376 B
    cudaFuncSetAttribute(fused_main, cudaFuncAttributeMaxDynamicSharedMemorySize, smem);
    fused_main<<<BT, 256, smem>>>(Afe, Bfd, Catt, gf1, bnf1,
                                  Wf2T, bf2, gf2, bnf2,
                                  W1fT, g1, bn1,
                                  W2Ts, b2s, out);
}

// round 4
// speedup vs baseline: 2.0305x; 2.0305x over previous
#include <cuda_runtime.h>
#include <cuda_bf16.h>
#include <cstdint>

#define EPSF 1e-5f

// ---------------- problem dims ----------------
#define BB 8
#define TT 128
#define UU 64
#define EE 768
#define HH 512
#define HH2 256
#define VV 1024
#define BT (BB*TT)   // 1024
#define BU (BB*UU)   // 512
#define RR (BT*UU)   // 65536 joint rows

// ---------------- scratch (device globals) ----------------
__device__ __align__(256) float g_big [RR*HH];
__device__ __align__(256) float g_pre [BT*HH];
__device__ __align__(256) float g_Afe [BT*HH];
__device__ __align__(256) float g_Bfd [BU*HH];
__device__ __align__(256) float g_Catt[BU*HH];
__device__ __align__(256) float g_b2s [VV];

#define DECL_SPLIT(name, n) \
    __device__ __align__(256) __nv_bfloat16 name##_h[n]; \
    __device__ __align__(256) __nv_bfloat16 name##_l[n];

DECL_SPLIT(g_enc,  BT*EE)
DECL_SPLIT(g_dec,  BU*EE)
DECL_SPLIT(g_encp, BT*HH)
DECL_SPLIT(g_decp, BU*HH)
DECL_SPLIT(g_tv,   BU*HH)
DECL_SPLIT(g_att,  BU*HH)
DECL_SPLIT(g_f,    RR*HH)      // reused for hx after stage B consumes f
DECL_SPLIT(g_fu,   RR*HH2)
DECL_SPLIT(g_We,  HH*EE)
DECL_SPLIT(g_Wd,  HH*EE)
DECL_SPLIT(g_Wf1, HH*HH)
DECL_SPLIT(g_Wv,  HH*HH)
DECL_SPLIT(g_Wo,  HH*HH)
DECL_SPLIT(g_W1a, HH*HH)
DECL_SPLIT(g_W1f, HH*HH2)
DECL_SPLIT(g_Wf2, HH2*HH)
DECL_SPLIT(g_W2,  VV*HH)

// ---------------- PTX helpers ----------------
__device__ __forceinline__ uint32_t smem_u32(const void* p) {
    uint32_t a;
    asm("{ .reg .u64 t; cvta.to.shared.u64 t, %1; cvt.u32.u64 %0, t; }" : "=r"(a) : "l"(p));
    return a;
}
#define CP_COMMIT() asm volatile("cp.async.commit_group;\n")
#define CP_WAIT(n)  asm volatile("cp.async.wait_group %0;\n" :: "n"(n))

__device__ __forceinline__ void cp16(uint32_t dst, const void* src) {
    asm volatile("cp.async.cg.shared.global [%0], [%1], 16;\n" :: "r"(dst), "l"(src));
}
__device__ __forceinline__ void ldmat_x4(uint32_t* r, uint32_t addr) {
    asm volatile("ldmatrix.sync.aligned.m8n8.x4.shared.b16 {%0,%1,%2,%3}, [%4];"
        : "=r"(r[0]), "=r"(r[1]), "=r"(r[2]), "=r"(r[3]) : "r"(addr));
}
__device__ __forceinline__ void mma_bf16(float* d, const uint32_t* a, const uint32_t* b) {
    asm volatile("mma.sync.aligned.m16n8k16.row.col.f32.bf16.bf16.f32 "
        "{%0,%1,%2,%3}, {%4,%5,%6,%7}, {%8,%9}, {%0,%1,%2,%3};"
        : "+f"(d[0]), "+f"(d[1]), "+f"(d[2]), "+f"(d[3])
        : "r"(a[0]), "r"(a[1]), "r"(a[2]), "r"(a[3]), "r"(b[0]), "r"(b[1]));
}

// ---------------- split helpers ----------------
__device__ __forceinline__ void split1(float x, __nv_bfloat16& h, __nv_bfloat16& l) {
    h = __float2bfloat16(x);
    l = __float2bfloat16(x - __bfloat162float(h));
}
__device__ __forceinline__ void split_store4(float y0, float y1, float y2, float y3,
                                             __nv_bfloat16* hi, __nv_bfloat16* lo, size_t idx) {
    union { __nv_bfloat16 b[4]; uint2 u; } H, L;
    split1(y0, H.b[0], L.b[0]); split1(y1, H.b[1], L.b[1]);
    split1(y2, H.b[2], L.b[2]); split1(y3, H.b[3], L.b[3]);
    *(uint2*)&hi[idx] = H.u;
    *(uint2*)&lo[idx] = L.u;
}
__device__ __forceinline__ float warp_sum(float v) {
#pragma unroll
    for (int o = 16; o; o >>= 1) v += __shfl_xor_sync(0xffffffffu, v, o);
    return v;
}

// ---------------- elementwise kernels ----------------
__global__ void split_w_k(const float* __restrict__ W, int ld, int koff, int cols,
                          const float* __restrict__ rscale,
                          __nv_bfloat16* __restrict__ hi, __nv_bfloat16* __restrict__ lo) {
    int row = blockIdx.x;
    float sc = rscale ? rscale[row] : 1.f;
    const float* src = W + (size_t)row * ld + koff;
    for (int j = threadIdx.x * 4; j < cols; j += blockDim.x * 4) {
        float4 t = *(const float4*)&src[j];
        split_store4(t.x * sc, t.y * sc, t.z * sc, t.w * sc, hi, lo, (size_t)row * cols + j);
    }
}

__global__ void b2s_k(const float* __restrict__ b2, const float* __restrict__ ssw,
                      float* __restrict__ o) {
    int i = threadIdx.x + blockIdx.x * blockDim.x;
    if (i < VV) o[i] = b2[i] * ssw[i];
}

// per-row LN + relu + split. one warp per row. N in {256, 512}
__global__ void ln_relu_split_k(const float* __restrict__ in, int N,
                                const float* __restrict__ g, const float* __restrict__ bv,
                                __nv_bfloat16* __restrict__ hi, __nv_bfloat16* __restrict__ lo) {
    int row = blockIdx.x * 8 + (threadIdx.x >> 5);
    int lane = threadIdx.x & 31;
    const float* x = in + (size_t)row * N;
    int nb = N >> 7;
    float4 v[4];
    float s = 0.f, sq = 0.f;
#pragma unroll
    for (int k = 0; k < 4; k++) {
        if (k < nb) {
            float4 t = *(const float4*)&x[k * 128 + lane * 4];
            v[k] = t;
            s += t.x + t.y + t.z + t.w;
            sq += t.x * t.x + t.y * t.y + t.z * t.z + t.w * t.w;
        }
    }
    s = warp_sum(s); sq = warp_sum(sq);
    float m = s / N, var = sq / N - m * m, rs = rsqrtf(var + EPSF);
#pragma unroll
    for (int k = 0; k < 4; k++) {
        if (k < nb) {
            int j = k * 128 + lane * 4;
            float4 gg = *(const float4*)&g[j];
            float4 bb = *(const float4*)&bv[j];
            float y0 = fmaxf((v[k].x - m) * rs * gg.x + bb.x, 0.f);
            float y1 = fmaxf((v[k].y - m) * rs * gg.y + bb.y, 0.f);
            float y2 = fmaxf((v[k].z - m) * rs * gg.z + bb.z, 0.f);
            float y3 = fmaxf((v[k].w - m) * rs * gg.w + bb.w, 0.f);
            split_store4(y0, y1, y2, y3, hi, lo, (size_t)row * N + j);
        }
    }
}

// f = LNrelu(Afe[bt] + Bfd[b,u]) -> split. one warp per joint row. N=512
__global__ void bigA_k(const float* __restrict__ Afe, const float* __restrict__ Bfd,
                       const float* __restrict__ g, const float* __restrict__ bv,
                       __nv_bfloat16* __restrict__ hi, __nv_bfloat16* __restrict__ lo) {
    int r = blockIdx.x * 8 + (threadIdx.x >> 5);
    int lane = threadIdx.x & 31;
    const float* A = Afe + (size_t)(r >> 6) * HH;
    const float* B = Bfd + (size_t)(((r >> 13) << 6) | (r & 63)) * HH;
    float4 v[4];
    float s = 0.f, sq = 0.f;
#pragma unroll
    for (int k = 0; k < 4; k++) {
        int j = k * 128 + lane * 4;
        float4 a = *(const float4*)&A[j];
        float4 b = *(const float4*)&B[j];
        float4 t = make_float4(a.x + b.x, a.y + b.y, a.z + b.z, a.w + b.w);
        v[k] = t;
        s += t.x + t.y + t.z + t.w;
        sq += t.x * t.x + t.y * t.y + t.z * t.z + t.w * t.w;
    }
    s = warp_sum(s); sq = warp_sum(sq);
    float m = s * (1.f / HH), var = sq * (1.f / HH) - m * m, rs = rsqrtf(var + EPSF);
#pragma unroll
    for (int k = 0; k < 4; k++) {
        int j = k * 128 + lane * 4;
        float4 gg = *(const float4*)&g[j];
        float4 bb = *(const float4*)&bv[j];
        float y0 = fmaxf((v[k].x - m) * rs * gg.x + bb.x, 0.f);
        float y1 = fmaxf((v[k].y - m) * rs * gg.y + bb.y, 0.f);
        float y2 = fmaxf((v[k].z - m) * rs * gg.z + bb.z, 0.f);
        float y3 = fmaxf((v[k].w - m) * rs * gg.w + bb.w, 0.f);
        split_store4(y0, y1, y2, y3, hi, lo, (size_t)r * HH + j);
    }
}

// ---------------- HMMA (mma.sync) GEMM ----------------
// OUT[M,N] = A[M,K] @ B[N,K]^T (+colbias[col]) (+rowbias via jointer map), fp32 out.
// A,B bf16 hi/lo split pairs. CTA tile 128x128, K chunk 32, 8 warps (2M x 4N),
// warp tile 64x32 = 4x4 m16n8k16. cp.async double buffer; smem rows padded to 80B.
#define PADK 40                 // smem row stride in bf16 elements (80B)
#define MAT_BYTES (128*PADK*2)  // 10240
#define STAGE_BYTES (4*MAT_BYTES)
#define GEMM_SMEM (2*STAGE_BYTES)   // 81920

__global__ void __launch_bounds__(256) gemm_tc(
    const __nv_bfloat16* __restrict__ Ahi, const __nv_bfloat16* __restrict__ Alo, int lda,
    const __nv_bfloat16* __restrict__ Bhi, const __nv_bfloat16* __restrict__ Blo, int ldb,
    const float* __restrict__ colbias, const float* __restrict__ rowbias,
    float* __restrict__ out, int ldo, int K) {
    extern __shared__ __align__(1024) char smem[];
    uint32_t sb = smem_u32(smem);
    int tid = threadIdx.x, lane = tid & 31, warp = tid >> 5;
    int warpM = warp & 1, warpN = warp >> 1;
    int row0 = blockIdx.y * 128, col0 = blockIdx.x * 128;

    const __nv_bfloat16* bases[4] = {
        Ahi + (size_t)row0 * lda, Alo + (size_t)row0 * lda,
        Bhi + (size_t)col0 * ldb, Blo + (size_t)col0 * ldb };
    int ldm[4] = { lda, lda, ldb, ldb };

    auto stage = [&](int c) {
        uint32_t dbase = sb + (uint32_t)(c & 1) * STAGE_BYTES;
        int k0 = c * 32;
#pragma unroll
        for (int i = 0; i < 8; i++) {
            int idx = tid + i * 256;
            int mat = idx >> 9, within = idx & 511;
            int row = within >> 2, cb = within & 3;
            const __nv_bfloat16* src = bases[mat] + (size_t)row * ldm[mat] + k0 + cb * 8;
            uint32_t dst = dbase + (uint32_t)(mat * MAT_BYTES + row * (PADK * 2) + cb * 16);
            cp16(dst, src);
        }
        CP_COMMIT();
    };

    float acc[4][4][4];
#pragma unroll
    for (int mt = 0; mt < 4; mt++)
#pragma unroll
        for (int nt = 0; nt < 4; nt++)
#pragma unroll
            for (int j = 0; j < 4; j++) acc[mt][nt][j] = 0.f;

    int NC = K >> 5;
    stage(0);
#pragma unroll 1
    for (int c = 0; c < NC; ++c) {
        if (c + 1 < NC) { stage(c + 1); CP_WAIT(1); }
        else            { CP_WAIT(0); }
        __syncthreads();
        uint32_t base = sb + (uint32_t)(c & 1) * STAGE_BYTES;

        // per-thread ldmatrix source rows
        int arow = warpM * 64 + ((lane >> 3) & 1) * 8 + (lane & 7);
        int brow = warpN * 32 + ((lane >> 4) & 1) * 8 + (lane & 7);
#pragma unroll
        for (int ks = 0; ks < 2; ks++) {
            uint32_t acolb = (uint32_t)((((lane >> 4) & 1) * 8 + ks * 16) * 2);
            uint32_t bcolb = (uint32_t)((((lane >> 3) & 1) * 8 + ks * 16) * 2);
            uint32_t ah[4][4], al[4][4], bh[4][2], bl[4][2];
#pragma unroll
            for (int mt = 0; mt < 4; mt++) {
                uint32_t a0 = base + (uint32_t)((arow + mt * 16) * (PADK * 2)) + acolb;
                ldmat_x4(ah[mt], a0);
                ldmat_x4(al[mt], a0 + MAT_BYTES);
            }
#pragma unroll
            for (int nt2 = 0; nt2 < 2; nt2++) {
                uint32_t r[4];
                uint32_t b0 = base + 2 * MAT_BYTES +
                              (uint32_t)((brow + nt2 * 16) * (PADK * 2)) + bcolb;
                ldmat_x4(r, b0);
                bh[nt2 * 2][0] = r[0]; bh[nt2 * 2][1] = r[1];
                bh[nt2 * 2 + 1][0] = r[2]; bh[nt2 * 2 + 1][1] = r[3];
                ldmat_x4(r, b0 + MAT_BYTES);
                bl[nt2 * 2][0] = r[0]; bl[nt2 * 2][1] = r[1];
                bl[nt2 * 2 + 1][0] = r[2]; bl[nt2 * 2 + 1][1] = r[3];
            }
#pragma unroll
            for (int mt = 0; mt < 4; mt++)
#pragma unroll
                for (int nt = 0; nt < 4; nt++) {
                    mma_bf16(acc[mt][nt], ah[mt], bh[nt]);
                    mma_bf16(acc[mt][nt], ah[mt], bl[nt]);
                    mma_bf16(acc[mt][nt], al[mt], bh[nt]);
                }
        }
        __syncthreads();
    }

    // ---- epilogue ----
    int trow = lane >> 2, tcol = (lane & 3) * 2;
#pragma unroll
    for (int mt = 0; mt < 4; mt++) {
        int r_g0 = row0 + warpM * 64 + mt * 16 + trow;
        int r_g1 = r_g0 + 8;
        const float* rb0 = nullptr;
        const float* rb1 = nullptr;
        if (rowbias) {
            rb0 = rowbias + (size_t)(((r_g0 >> 13) << 6) | (r_g0 & 63)) * HH;
            rb1 = rowbias + (size_t)(((r_g1 >> 13) << 6) | (r_g1 & 63)) * HH;
        }
#pragma unroll
        for (int nt = 0; nt < 4; nt++) {
            int c_g = col0 + warpN * 32 + nt * 8 + tcol;
            float y0 = acc[mt][nt][0], y1 = acc[mt][nt][1];
            float y2 = acc[mt][nt][2], y3 = acc[mt][nt][3];
            if (colbias) {
                float cb0 = colbias[c_g], cb1 = colbias[c_g + 1];
                y0 += cb0; y1 += cb1; y2 += cb0; y3 += cb1;
            }
            if (rb0) { y0 += rb0[c_g]; y1 += rb0[c_g + 1]; y2 += rb1[c_g]; y3 += rb1[c_g + 1]; }
            *(float2*)&out[(size_t)r_g0 * ldo + c_g] = make_float2(y0, y1);
            *(float2*)&out[(size_t)r_g1 * ldo + c_g] = make_float2(y2, y3);
        }
    }
}

// ---------------- host launcher ----------------
static inline void launch_gemm(const __nv_bfloat16* Ah, const __nv_bfloat16* Al, int lda,
                               const __nv_bfloat16* Bh, const __nv_bfloat16* Bl, int ldb,
                               const float* cbias, const float* rbias,
                               float* out, int ldo, int K, int M, int N) {
    cudaFuncSetAttribute(gemm_tc, cudaFuncAttributeMaxDynamicSharedMemorySize, GEMM_SMEM);
    dim3 grid(N / 128, M / 128);
    gemm_tc<<<grid, 256, GEMM_SMEM>>>(Ah, Al, lda, Bh, Bl, ldb, cbias, rbias, out, ldo, K);
}

extern "C" void kernel_launch(void* const* d_in, const int* in_sizes, int n_in,
                              void* d_out, int out_size) {
    const float* enc = (const float*)d_in[0];
    const float* dec = (const float*)d_in[1];
    const float* We  = (const float*)d_in[2];
    const float* be  = (const float*)d_in[3];
    const float* ge  = (const float*)d_in[4];
    const float* bne = (const float*)d_in[5];
    const float* Wd  = (const float*)d_in[6];
    const float* bd  = (const float*)d_in[7];
    const float* gd  = (const float*)d_in[8];
    const float* bnd = (const float*)d_in[9];
    const float* Wf1 = (const float*)d_in[10];
    const float* bf1 = (const float*)d_in[11];
    const float* gf1 = (const float*)d_in[12];
    const float* bnf1= (const float*)d_in[13];
    const float* Wf2 = (const float*)d_in[14];
    const float* bf2 = (const float*)d_in[15];
    const float* gf2 = (const float*)d_in[16];
    const float* bnf2= (const float*)d_in[17];
    const float* Wv  = (const float*)d_in[18];
    const float* bv  = (const float*)d_in[19];
    const float* Wo  = (const float*)d_in[20];
    const float* bo  = (const float*)d_in[21];
    const float* W1  = (const float*)d_in[22];
    const float* b1  = (const float*)d_in[23];
    const float* g1  = (const float*)d_in[24];
    const float* bn1 = (const float*)d_in[25];
    const float* W2  = (const float*)d_in[26];
    const float* b2  = (const float*)d_in[27];
    const float* ssw = (const float*)d_in[28];
    float* out = (float*)d_out;

    float *big, *pre, *Afe, *Bfd, *Catt, *b2s;
    cudaGetSymbolAddress((void**)&big,  g_big);
    cudaGetSymbolAddress((void**)&pre,  g_pre);
    cudaGetSymbolAddress((void**)&Afe,  g_Afe);
    cudaGetSymbolAddress((void**)&Bfd,  g_Bfd);
    cudaGetSymbolAddress((void**)&Catt, g_Catt);
    cudaGetSymbolAddress((void**)&b2s,  g_b2s);

#define GETS(name) \
    __nv_bfloat16 *name##h, *name##l; \
    cudaGetSymbolAddress((void**)&name##h, g_##name##_h); \
    cudaGetSymbolAddress((void**)&name##l, g_##name##_l);
    GETS(enc) GETS(dec) GETS(encp) GETS(decp) GETS(tv) GETS(att)
    GETS(f) GETS(fu)
    GETS(We) GETS(Wd) GETS(Wf1) GETS(Wv) GETS(Wo) GETS(W1a) GETS(W1f) GETS(Wf2) GETS(W2)
#undef GETS
    // hx aliases f (f is dead after stage B GEMM)
    __nv_bfloat16* hxh = fh;
    __nv_bfloat16* hxl = fl;

    // ---- weight / input splits ----
    split_w_k<<<HH, 192>>>(We,  EE, 0,   EE,  nullptr, Weh,  Wel);
    split_w_k<<<HH, 192>>>(Wd,  EE, 0,   EE,  nullptr, Wdh,  Wdl);
    split_w_k<<<HH, 192>>>(Wf1, HH, 0,   HH,  nullptr, Wf1h, Wf1l);
    split_w_k<<<HH, 192>>>(Wv,  HH, 0,   HH,  nullptr, Wvh,  Wvl);
    split_w_k<<<HH, 192>>>(Wo,  HH, 0,   HH,  nullptr, Woh,  Wol);
    split_w_k<<<HH, 192>>>(W1,  EE, HH2, HH,  nullptr, W1ah, W1al);
    split_w_k<<<HH, 192>>>(W1,  EE, 0,   HH2, nullptr, W1fh, W1fl);
    split_w_k<<<HH2,192>>>(Wf2, HH, 0,   HH,  nullptr, Wf2h, Wf2l);
    split_w_k<<<VV, 192>>>(W2,  HH, 0,   HH,  ssw,     W2h,  W2l);
    split_w_k<<<BT, 192>>>(enc, EE, 0,   EE,  nullptr, ench, encl);
    split_w_k<<<BU, 192>>>(dec, EE, 0,   EE,  nullptr, dech, decl);
    b2s_k<<<1, VV>>>(b2, ssw, b2s);

    // ---- preamble ----
    launch_gemm(ench, encl, EE, Weh, Wel, EE, be, nullptr, pre, HH, EE, BT, HH);
    ln_relu_split_k<<<BT / 8, 256>>>(pre, HH, ge, bne, encph, encpl);
    launch_gemm(dech, decl, EE, Wdh, Wdl, EE, bd, nullptr, pre, HH, EE, BU, HH);
    ln_relu_split_k<<<BU / 8, 256>>>(pre, HH, gd, bnd, decph, decpl);
    launch_gemm(encph, encpl, HH, Wf1h, Wf1l, HH, nullptr, nullptr, Afe, HH, HH, BT, HH);
    launch_gemm(decph, decpl, HH, Wf1h, Wf1l, HH, bf1, nullptr, Bfd, HH, HH, BU, HH);
    launch_gemm(decph, decpl, HH, Wvh, Wvl, HH, bv, nullptr, pre, HH, HH, BU, HH);
    split_w_k<<<BU, 192>>>(pre, HH, 0, HH, nullptr, tvh, tvl);
    launch_gemm(tvh, tvl, HH, Woh, Wol, HH, bo, nullptr, pre, HH, HH, BU, HH);
    split_w_k<<<BU, 192>>>(pre, HH, 0, HH, nullptr, atth, attl);
    launch_gemm(atth, attl, HH, W1ah, W1al, HH, b1, nullptr, Catt, HH, HH, BU, HH);

    // ---- main pipeline ----
    bigA_k<<<RR / 8, 256>>>(Afe, Bfd, gf1, bnf1, fh, fl);
    launch_gemm(fh, fl, HH, Wf2h, Wf2l, HH, bf2, nullptr, big, HH2, HH, RR, HH2);
    ln_relu_split_k<<<RR / 8, 256>>>(big, HH2, gf2, bnf2, fuh, ful);
    launch_gemm(fuh, ful, HH2, W1fh, W1fl, HH2, nullptr, Catt, big, HH, HH2, RR, HH);
    ln_relu_split_k<<<RR / 8, 256>>>(big, HH, g1, bn1, hxh, hxl);
    launch_gemm(hxh, hxl, HH, W2h, W2l, HH, b2s, nullptr, out, VV, HH, RR, VV);
}

// round 6
// speedup vs baseline: 2.3665x; 1.1655x over previous
#include <cuda_runtime.h>
#include <cuda_bf16.h>
#include <cstdint>

#define EPSF 1e-5f

// ---------------- problem dims ----------------
#define BB 8
#define TT 128
#define UU 64
#define EE 768
#define HH 512
#define HH2 256
#define VV 1024
#define BT (BB*TT)   // 1024
#define BU (BB*UU)   // 512
#define RR (BT*UU)   // 65536 joint rows

// ---------------- scratch (device globals; footprint kept <= round-4 level) ----------------
__device__ __align__(256) float g_big [RR*HH];   // 134MB: pre-LN buffer
__device__ __align__(256) float g_fbuf[RR*HH];   // 134MB: f split (bf16 hi|lo) THEN hx32 (fp32)
__device__ __align__(256) float g_W2f [VV*HH];   // 2MB: tf32-rounded W2*ssw
__device__ __align__(256) float g_pre [BT*HH];
__device__ __align__(256) float g_Afe [BT*HH];
__device__ __align__(256) float g_Bfd [BU*HH];
__device__ __align__(256) float g_Catt[BU*HH];
__device__ __align__(256) float g_b2s [VV];

#define DECL_SPLIT(name, n) \
    __device__ __align__(256) __nv_bfloat16 name##_h[n]; \
    __device__ __align__(256) __nv_bfloat16 name##_l[n];

DECL_SPLIT(g_enc,  BT*EE)
DECL_SPLIT(g_dec,  BU*EE)
DECL_SPLIT(g_encp, BT*HH)
DECL_SPLIT(g_decp, BU*HH)
DECL_SPLIT(g_tv,   BU*HH)
DECL_SPLIT(g_att,  BU*HH)
DECL_SPLIT(g_fu,   RR*HH2)   // 67MB
DECL_SPLIT(g_We,  HH*EE)
DECL_SPLIT(g_Wd,  HH*EE)
DECL_SPLIT(g_Wf1, HH*HH)
DECL_SPLIT(g_Wv,  HH*HH)
DECL_SPLIT(g_Wo,  HH*HH)
DECL_SPLIT(g_W1a, HH*HH)
DECL_SPLIT(g_W1f, HH*HH2)
DECL_SPLIT(g_Wf2, HH2*HH)

// ---------------- PTX helpers ----------------
__device__ __forceinline__ uint32_t smem_u32(const void* p) {
    uint32_t a;
    asm("{ .reg .u64 t; cvta.to.shared.u64 t, %1; cvt.u32.u64 %0, t; }" : "=r"(a) : "l"(p));
    return a;
}
#define CP_COMMIT() asm volatile("cp.async.commit_group;\n")
#define CP_WAIT(n)  asm volatile("cp.async.wait_group %0;\n" :: "n"(n))

__device__ __forceinline__ void cp16(uint32_t dst, const void* src) {
    asm volatile("cp.async.cg.shared.global [%0], [%1], 16;\n" :: "r"(dst), "l"(src));
}
__device__ __forceinline__ void ldmat_x4(uint32_t* r, uint32_t addr) {
    asm volatile("ldmatrix.sync.aligned.m8n8.x4.shared.b16 {%0,%1,%2,%3}, [%4];"
        : "=r"(r[0]), "=r"(r[1]), "=r"(r[2]), "=r"(r[3]) : "r"(addr));
}
__device__ __forceinline__ void mma_bf16(float* d, const uint32_t* a, const uint32_t* b) {
    asm volatile("mma.sync.aligned.m16n8k16.row.col.f32.bf16.bf16.f32 "
        "{%0,%1,%2,%3}, {%4,%5,%6,%7}, {%8,%9}, {%0,%1,%2,%3};"
        : "+f"(d[0]), "+f"(d[1]), "+f"(d[2]), "+f"(d[3])
        : "r"(a[0]), "r"(a[1]), "r"(a[2]), "r"(a[3]), "r"(b[0]), "r"(b[1]));
}
__device__ __forceinline__ void mma_tf32(float* d, const uint32_t* a, const uint32_t* b) {
    asm volatile("mma.sync.aligned.m16n8k8.row.col.f32.tf32.tf32.f32 "
        "{%0,%1,%2,%3}, {%4,%5,%6,%7}, {%8,%9}, {%0,%1,%2,%3};"
        : "+f"(d[0]), "+f"(d[1]), "+f"(d[2]), "+f"(d[3])
        : "r"(a[0]), "r"(a[1]), "r"(a[2]), "r"(a[3]), "r"(b[0]), "r"(b[1]));
}
__device__ __forceinline__ float tf32r(float x) {
    uint32_t u;
    asm("cvt.rna.tf32.f32 %0, %1;" : "=r"(u) : "f"(x));
    return __uint_as_float(u);
}

// ---------------- split helpers ----------------
__device__ __forceinline__ void split1(float x, __nv_bfloat16& h, __nv_bfloat16& l) {
    h = __float2bfloat16(x);
    l = __float2bfloat16(x - __bfloat162float(h));
}
__device__ __forceinline__ void split_store4(float y0, float y1, float y2, float y3,
                                             __nv_bfloat16* hi, __nv_bfloat16* lo, size_t idx) {
    union { __nv_bfloat16 b[4]; uint2 u; } H, L;
    split1(y0, H.b[0], L.b[0]); split1(y1, H.b[1], L.b[1]);
    split1(y2, H.b[2], L.b[2]); split1(y3, H.b[3], L.b[3]);
    *(uint2*)&hi[idx] = H.u;
    *(uint2*)&lo[idx] = L.u;
}
__device__ __forceinline__ float warp_sum(float v) {
#pragma unroll
    for (int o = 16; o; o >>= 1) v += __shfl_xor_sync(0xffffffffu, v, o);
    return v;
}

// ---------------- elementwise kernels ----------------
__global__ void split_w_k(const float* __restrict__ W, int ld, int koff, int cols,
                          const float* __restrict__ rscale,
                          __nv_bfloat16* __restrict__ hi, __nv_bfloat16* __restrict__ lo) {
    int row = blockIdx.x;
    float sc = rscale ? rscale[row] : 1.f;
    const float* src = W + (size_t)row * ld + koff;
    for (int j = threadIdx.x * 4; j < cols; j += blockDim.x * 4) {
        float4 t = *(const float4*)&src[j];
        split_store4(t.x * sc, t.y * sc, t.z * sc, t.w * sc, hi, lo, (size_t)row * cols + j);
    }
}

__global__ void b2s_k(const float* __restrict__ b2, const float* __restrict__ ssw,
                      float* __restrict__ o) {
    int i = threadIdx.x + blockIdx.x * blockDim.x;
    if (i < VV) o[i] = b2[i] * ssw[i];
}

// W2f = tf32_round(W2 * ssw[row])
__global__ void w2f_k(const float* __restrict__ W2, const float* __restrict__ ssw,
                      float* __restrict__ o) {
    int row = blockIdx.x;
    float sc = ssw[row];
    const float* src = W2 + (size_t)row * HH;
    float* dst = o + (size_t)row * HH;
    for (int j = threadIdx.x * 4; j < HH; j += blockDim.x * 4) {
        float4 t = *(const float4*)&src[j];
        dst[j]     = tf32r(t.x * sc);
        dst[j + 1] = tf32r(t.y * sc);
        dst[j + 2] = tf32r(t.z * sc);
        dst[j + 3] = tf32r(t.w * sc);
    }
}

// per-row LN + relu + split. one warp per row. N in {256, 512}
__global__ void ln_relu_split_k(const float* __restrict__ in, int N,
                                const float* __restrict__ g, const float* __restrict__ bv,
                                __nv_bfloat16* __restrict__ hi, __nv_bfloat16* __restrict__ lo) {
    int row = blockIdx.x * 8 + (threadIdx.x >> 5);
    int lane = threadIdx.x & 31;
    const float* x = in + (size_t)row * N;
    int nb = N >> 7;
    float4 v[4];
    float s = 0.f, sq = 0.f;
#pragma unroll
    for (int k = 0; k < 4; k++) {
        if (k < nb) {
            float4 t = *(const float4*)&x[k * 128 + lane * 4];
            v[k] = t;
            s += t.x + t.y + t.z + t.w;
            sq += t.x * t.x + t.y * t.y + t.z * t.z + t.w * t.w;
        }
    }
    s = warp_sum(s); sq = warp_sum(sq);
    float m = s / N, var = sq / N - m * m, rs = rsqrtf(var + EPSF);
#pragma unroll
    for (int k = 0; k < 4; k++) {
        if (k < nb) {
            int j = k * 128 + lane * 4;
            float4 gg = *(const float4*)&g[j];
            float4 bb = *(const float4*)&bv[j];
            float y0 = fmaxf((v[k].x - m) * rs * gg.x + bb.x, 0.f);
            float y1 = fmaxf((v[k].y - m) * rs * gg.y + bb.y, 0.f);
            float y2 = fmaxf((v[k].z - m) * rs * gg.z + bb.z, 0.f);
            float y3 = fmaxf((v[k].w - m) * rs * gg.w + bb.w, 0.f);
            split_store4(y0, y1, y2, y3, hi, lo, (size_t)row * N + j);
        }
    }
}

// per-row LN + relu -> tf32-rounded fp32 out. one warp per row. N=512.
__global__ void ln_relu_tf_k(const float* __restrict__ in,
                             const float* __restrict__ g, const float* __restrict__ bv,
                             float* __restrict__ out) {
    int row = blockIdx.x * 8 + (threadIdx.x >> 5);
    int lane = threadIdx.x & 31;
    const float* x = in + (size_t)row * HH;
    float4 v[4];
    float s = 0.f, sq = 0.f;
#pragma unroll
    for (int k = 0; k < 4; k++) {
        float4 t = *(const float4*)&x[k * 128 + lane * 4];
        v[k] = t;
        s += t.x + t.y + t.z + t.w;
        sq += t.x * t.x + t.y * t.y + t.z * t.z + t.w * t.w;
    }
    s = warp_sum(s); sq = warp_sum(sq);
    float m = s * (1.f / HH), var = sq * (1.f / HH) - m * m, rs = rsqrtf(var + EPSF);
#pragma unroll
    for (int k = 0; k < 4; k++) {
        int j = k * 128 + lane * 4;
        float4 gg = *(const float4*)&g[j];
        float4 bb = *(const float4*)&bv[j];
        float4 y;
        y.x = tf32r(fmaxf((v[k].x - m) * rs * gg.x + bb.x, 0.f));
        y.y = tf32r(fmaxf((v[k].y - m) * rs * gg.y + bb.y, 0.f));
        y.z = tf32r(fmaxf((v[k].z - m) * rs * gg.z + bb.z, 0.f));
        y.w = tf32r(fmaxf((v[k].w - m) * rs * gg.w + bb.w, 0.f));
        *(float4*)&out[(size_t)row * HH + j] = y;
    }
}

// f = LNrelu(Afe[bt] + Bfd[b,u]) -> split. one warp per joint row. N=512
__global__ void bigA_k(const float* __restrict__ Afe, const float* __restrict__ Bfd,
                       const float* __restrict__ g, const float* __restrict__ bv,
                       __nv_bfloat16* __restrict__ hi, __nv_bfloat16* __restrict__ lo) {
    int r = blockIdx.x * 8 + (threadIdx.x >> 5);
    int lane = threadIdx.x & 31;
    const float* A = Afe + (size_t)(r >> 6) * HH;
    const float* B = Bfd + (size_t)(((r >> 13) << 6) | (r & 63)) * HH;
    float4 v[4];
    float s = 0.f, sq = 0.f;
#pragma unroll
    for (int k = 0; k < 4; k++) {
        int j = k * 128 + lane * 4;
        float4 a = *(const float4*)&A[j];
        float4 b = *(const float4*)&B[j];
        float4 t = make_float4(a.x + b.x, a.y + b.y, a.z + b.z, a.w + b.w);
        v[k] = t;
        s += t.x + t.y + t.z + t.w;
        sq += t.x * t.x + t.y * t.y + t.z * t.z + t.w * t.w;
    }
    s = warp_sum(s); sq = warp_sum(sq);
    float m = s * (1.f / HH), var = sq * (1.f / HH) - m * m, rs = rsqrtf(var + EPSF);
#pragma unroll
    for (int k = 0; k < 4; k++) {
        int j = k * 128 + lane * 4;
        float4 gg = *(const float4*)&g[j];
        float4 bb = *(const float4*)&bv[j];
        float y0 = fmaxf((v[k].x - m) * rs * gg.x + bb.x, 0.f);
        float y1 = fmaxf((v[k].y - m) * rs * gg.y + bb.y, 0.f);
        float y2 = fmaxf((v[k].z - m) * rs * gg.z + bb.z, 0.f);
        float y3 = fmaxf((v[k].w - m) * rs * gg.w + bb.w, 0.f);
        split_store4(y0, y1, y2, y3, hi, lo, (size_t)r * HH + j);
    }
}

// ---------------- HMMA bf16 split GEMM (unchanged from round 4) ----------------
#define PADK 40                 // smem row stride in bf16 elements (80B)
#define MAT_BYTES (128*PADK*2)  // 10240
#define STAGE_BYTES (4*MAT_BYTES)
#define GEMM_SMEM (2*STAGE_BYTES)   // 81920

__global__ void __launch_bounds__(256) gemm_tc(
    const __nv_bfloat16* __restrict__ Ahi, const __nv_bfloat16* __restrict__ Alo, int lda,
    const __nv_bfloat16* __restrict__ Bhi, const __nv_bfloat16* __restrict__ Blo, int ldb,
    const float* __restrict__ colbias, const float* __restrict__ rowbias,
    float* __restrict__ out, int ldo, int K) {
    extern __shared__ __align__(1024) char smem[];
    uint32_t sb = smem_u32(smem);
    int tid = threadIdx.x, lane = tid & 31, warp = tid >> 5;
    int warpM = warp & 1, warpN = warp >> 1;
    int row0 = blockIdx.y * 128, col0 = blockIdx.x * 128;

    const __nv_bfloat16* bases[4] = {
        Ahi + (size_t)row0 * lda, Alo + (size_t)row0 * lda,
        Bhi + (size_t)col0 * ldb, Blo + (size_t)col0 * ldb };
    int ldm[4] = { lda, lda, ldb, ldb };

    auto stage = [&](int c) {
        uint32_t dbase = sb + (uint32_t)(c & 1) * STAGE_BYTES;
        int k0 = c * 32;
#pragma unroll
        for (int i = 0; i < 8; i++) {
            int idx = tid + i * 256;
            int mat = idx >> 9, within = idx & 511;
            int row = within >> 2, cb = within & 3;
            const __nv_bfloat16* src = bases[mat] + (size_t)row * ldm[mat] + k0 + cb * 8;
            uint32_t dst = dbase + (uint32_t)(mat * MAT_BYTES + row * (PADK * 2) + cb * 16);
            cp16(dst, src);
        }
        CP_COMMIT();
    };

    float acc[4][4][4];
#pragma unroll
    for (int mt = 0; mt < 4; mt++)
#pragma unroll
        for (int nt = 0; nt < 4; nt++)
#pragma unroll
            for (int j = 0; j < 4; j++) acc[mt][nt][j] = 0.f;

    int NC = K >> 5;
    stage(0);
#pragma unroll 1
    for (int c = 0; c < NC; ++c) {
        if (c + 1 < NC) { stage(c + 1); CP_WAIT(1); }
        else            { CP_WAIT(0); }
        __syncthreads();
        uint32_t base = sb + (uint32_t)(c & 1) * STAGE_BYTES;

        int arow = warpM * 64 + ((lane >> 3) & 1) * 8 + (lane & 7);
        int brow = warpN * 32 + ((lane >> 4) & 1) * 8 + (lane & 7);
#pragma unroll
        for (int ks = 0; ks < 2; ks++) {
            uint32_t acolb = (uint32_t)((((lane >> 4) & 1) * 8 + ks * 16) * 2);
            uint32_t bcolb = (uint32_t)((((lane >> 3) & 1) * 8 + ks * 16) * 2);
            uint32_t ah[4][4], al[4][4], bh[4][2], bl[4][2];
#pragma unroll
            for (int mt = 0; mt < 4; mt++) {
                uint32_t a0 = base + (uint32_t)((arow + mt * 16) * (PADK * 2)) + acolb;
                ldmat_x4(ah[mt], a0);
                ldmat_x4(al[mt], a0 + MAT_BYTES);
            }
#pragma unroll
            for (int nt2 = 0; nt2 < 2; nt2++) {
                uint32_t r[4];
                uint32_t b0 = base + 2 * MAT_BYTES +
                              (uint32_t)((brow + nt2 * 16) * (PADK * 2)) + bcolb;
                ldmat_x4(r, b0);
                bh[nt2 * 2][0] = r[0]; bh[nt2 * 2][1] = r[1];
                bh[nt2 * 2 + 1][0] = r[2]; bh[nt2 * 2 + 1][1] = r[3];
                ldmat_x4(r, b0 + MAT_BYTES);
                bl[nt2 * 2][0] = r[0]; bl[nt2 * 2][1] = r[1];
                bl[nt2 * 2 + 1][0] = r[2]; bl[nt2 * 2 + 1][1] = r[3];
            }
#pragma unroll
            for (int mt = 0; mt < 4; mt++)
#pragma unroll
                for (int nt = 0; nt < 4; nt++) {
                    mma_bf16(acc[mt][nt], ah[mt], bh[nt]);
                    mma_bf16(acc[mt][nt], ah[mt], bl[nt]);
                    mma_bf16(acc[mt][nt], al[mt], bh[nt]);
                }
        }
        __syncthreads();
    }

    // ---- epilogue ----
    int trow = lane >> 2, tcol = (lane & 3) * 2;
#pragma unroll
    for (int mt = 0; mt < 4; mt++) {
        int r_g0 = row0 + warpM * 64 + mt * 16 + trow;
        int r_g1 = r_g0 + 8;
        const float* rb0 = nullptr;
        const float* rb1 = nullptr;
        if (rowbias) {
            rb0 = rowbias + (size_t)(((r_g0 >> 13) << 6) | (r_g0 & 63)) * HH;
            rb1 = rowbias + (size_t)(((r_g1 >> 13) << 6) | (r_g1 & 63)) * HH;
        }
#pragma unroll
        for (int nt = 0; nt < 4; nt++) {
            int c_g = col0 + warpN * 32 + nt * 8 + tcol;
            float y0 = acc[mt][nt][0], y1 = acc[mt][nt][1];
            float y2 = acc[mt][nt][2], y3 = acc[mt][nt][3];
            if (colbias) {
                float cb0 = colbias[c_g], cb1 = colbias[c_g + 1];
                y0 += cb0; y1 += cb1; y2 += cb0; y3 += cb1;
            }
            if (rb0) { y0 += rb0[c_g]; y1 += rb0[c_g + 1]; y2 += rb1[c_g]; y3 += rb1[c_g + 1]; }
            *(float2*)&out[(size_t)r_g0 * ldo + c_g] = make_float2(y0, y1);
            *(float2*)&out[(size_t)r_g1 * ldo + c_g] = make_float2(y2, y3);
        }
    }
}

// ---------------- TF32 single-pass GEMM (stage D) ----------------
// OUT[M,N] = A[M,K] @ B[N,K]^T + colbias. A,B fp32 pre-rounded to tf32.
// CTA 128x128, 8 warps (2M x 4N), warp 64x32 = 4x4 m16n8k8 per k8.
// K chunk 32 double-buffered. smem row stride 36 fp32 (144B) -> conflict-free.
#define TF_PAD 36
#define TF_TILE_BYTES (128*TF_PAD*4)      // 18432
#define TF_STAGE (2*TF_TILE_BYTES)        // 36864
#define TF_SMEM (2*TF_STAGE)              // 73728

__global__ void __launch_bounds__(256) gemm_tf32(
    const float* __restrict__ A, int lda,
    const float* __restrict__ B, int ldb,
    const float* __restrict__ colbias,
    float* __restrict__ out, int ldo, int K) {
    extern __shared__ __align__(1024) char smem[];
    uint32_t sb = smem_u32(smem);
    int tid = threadIdx.x, lane = tid & 31, warp = tid >> 5;
    int warpM = warp & 1, warpN = warp >> 1;
    int row0 = blockIdx.y * 128, col0 = blockIdx.x * 128;

    const float* Abase = A + (size_t)row0 * lda;
    const float* Bbase = B + (size_t)col0 * ldb;

    auto stage = [&](int c) {
        uint32_t dbase = sb + (uint32_t)(c & 1) * TF_STAGE;
        int k0 = c * 32;
#pragma unroll
        for (int i = 0; i < 8; i++) {
            int idx = tid + i * 256;                 // 2048 chunks of 16B
            int mat = idx >> 10, within = idx & 1023;
            int row = within >> 3, cb = within & 7;
            const float* src = (mat ? Bbase + (size_t)row * ldb : Abase + (size_t)row * lda)
                               + k0 + cb * 4;
            uint32_t dst = dbase + (uint32_t)(mat * TF_TILE_BYTES + row * (TF_PAD * 4) + cb * 16);
            cp16(dst, src);
        }
        CP_COMMIT();
    };

    float acc[4][4][4];
#pragma unroll
    for (int mt = 0; mt < 4; mt++)
#pragma unroll
        for (int nt = 0; nt < 4; nt++)
#pragma unroll
            for (int j = 0; j < 4; j++) acc[mt][nt][j] = 0.f;

    int NC = K >> 5;
    int sub = lane >> 3, r8 = lane & 7;
    stage(0);
#pragma unroll 1
    for (int c = 0; c < NC; ++c) {
        if (c + 1 < NC) { stage(c + 1); CP_WAIT(1); }
        else            { CP_WAIT(0); }
        __syncthreads();
        uint32_t base = sb + (uint32_t)(c & 1) * TF_STAGE;
#pragma unroll
        for (int kb = 0; kb < 4; kb++) {
            uint32_t colb = (uint32_t)(kb * 32 + (sub >> 1) * 16);
            uint32_t a[4][4], b[4][2];
#pragma unroll
            for (int mt = 0; mt < 4; mt++) {
                int row = warpM * 64 + mt * 16 + (sub & 1) * 8 + r8;
                ldmat_x4(a[mt], base + (uint32_t)(row * (TF_PAD * 4)) + colb);
            }
#pragma unroll
            for (int bt = 0; bt < 2; bt++) {
                uint32_t r[4];
                int nrow = warpN * 32 + bt * 16 + (sub & 1) * 8 + r8;
                ldmat_x4(r, base + TF_TILE_BYTES + (uint32_t)(nrow * (TF_PAD * 4)) + colb);
                b[bt * 2][0] = r[0];     b[bt * 2][1] = r[2];
                b[bt * 2 + 1][0] = r[1]; b[bt * 2 + 1][1] = r[3];
            }
#pragma unroll
            for (int mt = 0; mt < 4; mt++)
#pragma unroll
                for (int nt = 0; nt < 4; nt++)
                    mma_tf32(acc[mt][nt], a[mt], b[nt]);
        }
        __syncthreads();
    }

    // ---- epilogue ----
    int trow = lane >> 2, tcol = (lane & 3) * 2;
#pragma unroll
    for (int mt = 0; mt < 4; mt++) {
        int r_g0 = row0 + warpM * 64 + mt * 16 + trow;
        int r_g1 = r_g0 + 8;
#pragma unroll
        for (int nt = 0; nt < 4; nt++) {
            int c_g = col0 + warpN * 32 + nt * 8 + tcol;
            float cb0 = colbias[c_g], cb1 = colbias[c_g + 1];
            *(float2*)&out[(size_t)r_g0 * ldo + c_g] =
                make_float2(acc[mt][nt][0] + cb0, acc[mt][nt][1] + cb1);
            *(float2*)&out[(size_t)r_g1 * ldo + c_g] =
                make_float2(acc[mt][nt][2] + cb0, acc[mt][nt][3] + cb1);
        }
    }
}

// ---------------- host launcher ----------------
static inline void launch_gemm(const __nv_bfloat16* Ah, const __nv_bfloat16* Al, int lda,
                               const __nv_bfloat16* Bh, const __nv_bfloat16* Bl, int ldb,
                               const float* cbias, const float* rbias,
                               float* out, int ldo, int K, int M, int N) {
    cudaFuncSetAttribute(gemm_tc, cudaFuncAttributeMaxDynamicSharedMemorySize, GEMM_SMEM);
    dim3 grid(N / 128, M / 128);
    gemm_tc<<<grid, 256, GEMM_SMEM>>>(Ah, Al, lda, Bh, Bl, ldb, cbias, rbias, out, ldo, K);
}

extern "C" void kernel_launch(void* const* d_in, const int* in_sizes, int n_in,
                              void* d_out, int out_size) {
    const float* enc = (const float*)d_in[0];
    const float* dec = (const float*)d_in[1];
    const float* We  = (const float*)d_in[2];
    const float* be  = (const float*)d_in[3];
    const float* ge  = (const float*)d_in[4];
    const float* bne = (const float*)d_in[5];
    const float* Wd  = (const float*)d_in[6];
    const float* bd  = (const float*)d_in[7];
    const float* gd  = (const float*)d_in[8];
    const float* bnd = (const float*)d_in[9];
    const float* Wf1 = (const float*)d_in[10];
    const float* bf1 = (const float*)d_in[11];
    const float* gf1 = (const float*)d_in[12];
    const float* bnf1= (const float*)d_in[13];
    const float* Wf2 = (const float*)d_in[14];
    const float* bf2 = (const float*)d_in[15];
    const float* gf2 = (const float*)d_in[16];
    const float* bnf2= (const float*)d_in[17];
    const float* Wv  = (const float*)d_in[18];
    const float* bv  = (const float*)d_in[19];
    const float* Wo  = (const float*)d_in[20];
    const float* bo  = (const float*)d_in[21];
    const float* W1  = (const float*)d_in[22];
    const float* b1  = (const float*)d_in[23];
    const float* g1  = (const float*)d_in[24];
    const float* bn1 = (const float*)d_in[25];
    const float* W2  = (const float*)d_in[26];
    const float* b2  = (const float*)d_in[27];
    const float* ssw = (const float*)d_in[28];
    float* out = (float*)d_out;

    float *big, *fbuf, *W2f, *pre, *Afe, *Bfd, *Catt, *b2s;
    cudaGetSymbolAddress((void**)&big,  g_big);
    cudaGetSymbolAddress((void**)&fbuf, g_fbuf);
    cudaGetSymbolAddress((void**)&W2f,  g_W2f);
    cudaGetSymbolAddress((void**)&pre,  g_pre);
    cudaGetSymbolAddress((void**)&Afe,  g_Afe);
    cudaGetSymbolAddress((void**)&Bfd,  g_Bfd);
    cudaGetSymbolAddress((void**)&Catt, g_Catt);
    cudaGetSymbolAddress((void**)&b2s,  g_b2s);

#define GETS(name) \
    __nv_bfloat16 *name##h, *name##l; \
    cudaGetSymbolAddress((void**)&name##h, g_##name##_h); \
    cudaGetSymbolAddress((void**)&name##l, g_##name##_l);
    GETS(enc) GETS(dec) GETS(encp) GETS(decp) GETS(tv) GETS(att)
    GETS(fu)
    GETS(We) GETS(Wd) GETS(Wf1) GETS(Wv) GETS(Wo) GETS(W1a) GETS(W1f) GETS(Wf2)
#undef GETS
    // f split lives in fbuf's 134MB; hx32 reuses the same buffer after f is dead.
    __nv_bfloat16* fh = (__nv_bfloat16*)fbuf;
    __nv_bfloat16* fl = fh + (size_t)RR * HH;
    float* hx32 = fbuf;

    // ---- weight / input prep ----
    split_w_k<<<HH, 192>>>(We,  EE, 0,   EE,  nullptr, Weh,  Wel);
    split_w_k<<<HH, 192>>>(Wd,  EE, 0,   EE,  nullptr, Wdh,  Wdl);
    split_w_k<<<HH, 192>>>(Wf1, HH, 0,   HH,  nullptr, Wf1h, Wf1l);
    split_w_k<<<HH, 192>>>(Wv,  HH, 0,   HH,  nullptr, Wvh,  Wvl);
    split_w_k<<<HH, 192>>>(Wo,  HH, 0,   HH,  nullptr, Woh,  Wol);
    split_w_k<<<HH, 192>>>(W1,  EE, HH2, HH,  nullptr, W1ah, W1al);
    split_w_k<<<HH, 192>>>(W1,  EE, 0,   HH2, nullptr, W1fh, W1fl);
    split_w_k<<<HH2,192>>>(Wf2, HH, 0,   HH,  nullptr, Wf2h, Wf2l);
    w2f_k<<<VV, 128>>>(W2, ssw, W2f);
    split_w_k<<<BT, 192>>>(enc, EE, 0,   EE,  nullptr, ench, encl);
    split_w_k<<<BU, 192>>>(dec, EE, 0,   EE,  nullptr, dech, decl);
    b2s_k<<<1, VV>>>(b2, ssw, b2s);

    // ---- preamble ----
    launch_gemm(ench, encl, EE, Weh, Wel, EE, be, nullptr, pre, HH, EE, BT, HH);
    ln_relu_split_k<<<BT / 8, 256>>>(pre, HH, ge, bne, encph, encpl);
    launch_gemm(dech, decl, EE, Wdh, Wdl, EE, bd, nullptr, pre, HH, EE, BU, HH);
    ln_relu_split_k<<<BU / 8, 256>>>(pre, HH, gd, bnd, decph, decpl);
    launch_gemm(encph, encpl, HH, Wf1h, Wf1l, HH, nullptr, nullptr, Afe, HH, HH, BT, HH);
    launch_gemm(decph, decpl, HH, Wf1h, Wf1l, HH, bf1, nullptr, Bfd, HH, HH, BU, HH);
    launch_gemm(decph, decpl, HH, Wvh, Wvl, HH, bv, nullptr, pre, HH, HH, BU, HH);
    split_w_k<<<BU, 192>>>(pre, HH, 0, HH, nullptr, tvh, tvl);
    launch_gemm(tvh, tvl, HH, Woh, Wol, HH, bo, nullptr, pre, HH, HH, BU, HH);
    split_w_k<<<BU, 192>>>(pre, HH, 0, HH, nullptr, atth, attl);
    launch_gemm(atth, attl, HH, W1ah, W1al, HH, b1, nullptr, Catt, HH, HH, BU, HH);

    // ---- main pipeline ----
    bigA_k<<<RR / 8, 256>>>(Afe, Bfd, gf1, bnf1, fh, fl);
    launch_gemm(fh, fl, HH, Wf2h, Wf2l, HH, bf2, nullptr, big, HH2, HH, RR, HH2);
    ln_relu_split_k<<<RR / 8, 256>>>(big, HH2, gf2, bnf2, fuh, ful);
    launch_gemm(fuh, ful, HH2, W1fh, W1fl, HH2, nullptr, Catt, big, HH, HH2, RR, HH);
    // f (in fbuf) is dead now; hx32 overwrites fbuf
    ln_relu_tf_k<<<RR / 8, 256>>>(big, g1, bn1, hx32);
    // stage D: tf32 single pass
    cudaFuncSetAttribute(gemm_tf32, cudaFuncAttributeMaxDynamicSharedMemorySize, TF_SMEM);
    gemm_tf32<<<dim3(VV / 128, RR / 128), 256, TF_SMEM>>>(hx32, HH, W2f, HH, b2s, out, VV, HH);
}